// round 14
// baseline (speedup 1.0000x reference)
#include <cuda_runtime.h>
#include <cstdint>

#define N_NODES 50000
#define N_EDGES 800000

// Scratch: __device__ globals (allocation is forbidden)
__device__ __align__(16) float g_xw[N_NODES * 64];     // x @ Wl1^T
__device__ __align__(16) float g_xr[N_NODES * 64];     // x @ Wr1^T
__device__ __align__(16) float g_aggr1[N_NODES * 64];  // segsum(xw)
__device__ __align__(16) float g_h[N_NODES * 64];      // layer-1 output
__device__ __align__(16) float g_hw[N_NODES * 32];     // h @ Wl2^T
__device__ __align__(16) float g_hr[N_NODES * 32];     // h @ Wr2^T
__device__ __align__(16) float g_aggr2[N_NODES * 32];  // segsum(hw)
__device__ __align__(16) float g_cnt[N_NODES];

// ---------------------------------------------------------------------------
// Edge aggregation, F-dim rows: thread = (edge, float4 chunk).
// red.global.add.v4.f32 no-return reductions.
// ---------------------------------------------------------------------------
template <int F>
__global__ void edge_aggregate_kernel(const float* __restrict__ feat,
                                      const int* __restrict__ ei,
                                      float* __restrict__ aggr,
                                      float* __restrict__ cnt,
                                      int do_count)
{
    constexpr int C   = F / 4;
    constexpr int LOG = (F == 64) ? 4 : 3;
    int idx = blockIdx.x * blockDim.x + threadIdx.x;
    const int total = N_EDGES * C;
    if (idx >= total) return;
    int e = idx >> LOG;
    int c = idx & (C - 1);

    int src = ei[e];
    int dst = ei[N_EDGES + e];

    float4 v = __ldg((const float4*)(feat + (size_t)src * F) + c);

    float* p = aggr + (size_t)dst * F + c * 4;
    asm volatile("red.global.add.v4.f32 [%0], {%1, %2, %3, %4};"
                 :: "l"(p), "f"(v.x), "f"(v.y), "f"(v.z), "f"(v.w)
                 : "memory");

    if (do_count && c == 0) {
        atomicAdd(cnt + dst, 1.0f);
    }
}

// Component permute: out[i] = in[i ^ p], p in {0,1,2,3}
__device__ __forceinline__ float4 perm4(float4 v, int p)
{
    if (p & 1) { float t = v.x; v.x = v.y; v.y = t; t = v.z; v.z = v.w; v.w = t; }
    if (p & 2) { float t = v.x; v.x = v.z; v.z = t; t = v.y; v.y = v.w; v.w = t; }
    return v;
}

// ---------------------------------------------------------------------------
// Dual GEMV: ya = x@Wa^T, yb = x@Wb^T in ONE pass over x.
//  - 256 threads (8 warps); warp = 32 nodes (lane = node) x one 8-output slice
//  - weight LDS.128s warp-uniform (broadcast, 1 wavefront)
//  - feature scalar k of node nl stored at nl*64 + (k ^ (nl&31)) -> for fixed
//    k the 32 lanes hit 32 distinct banks (validated in R8: L1 75% -> 51%)
//  - 8 outputs per matrix per thread: ~50 regs -> 5 blocks/SM;
//    SMEM 40KB (OUT=64) / 32KB (OUT=32) -> occ ~62% (R10 bound was occ=20%)
//  - exact-cover grid, no stride loop
// ---------------------------------------------------------------------------
template <int OUT>
__global__ void __launch_bounds__(256)
gemv_dual_kernel(const float* __restrict__ x,
                 const float* __restrict__ Wa,
                 const float* __restrict__ Wb,
                 float* __restrict__ ya,
                 float* __restrict__ yb)
{
    constexpr int IN     = 64;
    constexpr int SLICES = OUT / 8;       // 8 (OUT=64) or 4 (OUT=32)
    constexpr int GROUPS = 8 / SLICES;    // 1 or 2
    constexpr int NPB    = 32 * GROUPS;   // 32 or 64 nodes per block

    __shared__ float sWa[IN * OUT];       // transposed: [k*OUT + t]
    __shared__ float sWb[IN * OUT];
    __shared__ float sx[NPB * IN];        // swizzled feature rows
    // OUT=64: 16K+16K+8K = 40K;  OUT=32: 8K+8K+16K = 32K

    const int tid   = threadIdx.x;
    const int wid   = tid >> 5;
    const int lane  = tid & 31;
    const int slice = wid % SLICES;
    const int group = wid / SLICES;
    const int nloc  = group * 32 + lane;  // nloc & 31 == lane

    // Stage both weight matrices transposed: sW[k*OUT + t] = W[t*IN + k]
    for (int i = tid; i < IN * OUT; i += 256) {
        int t = i % OUT;
        int k = i / OUT;
        sWa[i] = __ldg(&Wa[t * IN + k]);
        sWb[i] = __ldg(&Wb[t * IN + k]);
    }

    // Stage feature rows, scalar-XOR swizzled
    const int base = blockIdx.x * NPB;
    for (int i = tid; i < NPB * (IN / 4); i += 256) {
        int nl = i / (IN / 4);
        int kq = i % (IN / 4);
        int n  = base + nl;
        if (n < N_NODES) {
            float4 xv = __ldg((const float4*)(x + (size_t)n * IN + kq * 4));
            int m    = nl & 31;
            int slot = kq ^ (m >> 2);
            ((float4*)(sx + nl * IN))[slot] = perm4(xv, m & 3);
        }
    }
    __syncthreads();

    int n = base + nloc;
    if (n >= N_NODES) return;

    float4 a0 = {0,0,0,0}, a1 = {0,0,0,0};   // Wa accumulators (8 outputs)
    float4 c0 = {0,0,0,0}, c1 = {0,0,0,0};   // Wb accumulators
    const float* px = sx + nloc * IN;
#pragma unroll 8
    for (int k = 0; k < IN; k++) {
        float xv = px[k ^ lane];
        const float4* wa = (const float4*)(sWa + k * OUT + slice * 8);
        const float4* wb = (const float4*)(sWb + k * OUT + slice * 8);
        float4 wa0 = wa[0], wa1 = wa[1];
        float4 wb0 = wb[0], wb1 = wb[1];
        a0.x += xv * wa0.x; a0.y += xv * wa0.y;
        a0.z += xv * wa0.z; a0.w += xv * wa0.w;
        a1.x += xv * wa1.x; a1.y += xv * wa1.y;
        a1.z += xv * wa1.z; a1.w += xv * wa1.w;
        c0.x += xv * wb0.x; c0.y += xv * wb0.y;
        c0.z += xv * wb0.z; c0.w += xv * wb0.w;
        c1.x += xv * wb1.x; c1.y += xv * wb1.y;
        c1.z += xv * wb1.z; c1.w += xv * wb1.w;
    }
    float4* pa = (float4*)(ya + (size_t)n * OUT + slice * 8);
    float4* pb = (float4*)(yb + (size_t)n * OUT + slice * 8);
    pa[0] = a0; pa[1] = a1;
    pb[0] = c0; pb[1] = c1;
}

// ---------------------------------------------------------------------------
// Elementwise combine: y = act( aggr/max(cnt,1) + bias + xr )
// Pure streaming kernel; float4 per thread.
// ---------------------------------------------------------------------------
template <int F, bool RELU>
__global__ void combine_kernel(const float* __restrict__ aggr,
                               const float* __restrict__ xr,
                               const float* __restrict__ cnt,
                               const float* __restrict__ bias,
                               float* __restrict__ y)
{
    constexpr int C = F / 4;
    int idx = blockIdx.x * blockDim.x + threadIdx.x;
    const int total = N_NODES * C;
    if (idx >= total) return;
    int n = idx / C;
    int q = idx % C;

    float inv = 1.0f / fmaxf(__ldg(&cnt[n]), 1.0f);
    float4 a = __ldg((const float4*)aggr + idx);
    float4 r = __ldg((const float4*)xr + idx);
    float4 b = __ldg((const float4*)bias + q);

    float4 o;
    o.x = a.x * inv + b.x + r.x;
    o.y = a.y * inv + b.y + r.y;
    o.z = a.z * inv + b.z + r.z;
    o.w = a.w * inv + b.w + r.w;
    if (RELU) {
        o.x = fmaxf(o.x, 0.f); o.y = fmaxf(o.y, 0.f);
        o.z = fmaxf(o.z, 0.f); o.w = fmaxf(o.w, 0.f);
    }
    ((float4*)y)[idx] = o;
}

// ---------------------------------------------------------------------------
// Launch. Transform-then-aggregate (segment_sum is linear):
//  L1: {xw,xr} = x@{Wl1,Wr1}^T; aggr1 = segsum(xw); h = relu(aggr1/cnt+bl1+xr)
//  L2: {hw,hr} = h@{Wl2,Wr2}^T; aggr2 = segsum(hw); out = aggr2/cnt+bl2+hr
// ---------------------------------------------------------------------------
extern "C" void kernel_launch(void* const* d_in, const int* in_sizes, int n_in,
                              void* d_out, int out_size)
{
    const float* x   = (const float*)d_in[0];
    const int*   ei  = (const int*)d_in[1];
    const float* Wl1 = (const float*)d_in[2];
    const float* bl1 = (const float*)d_in[3];
    const float* Wr1 = (const float*)d_in[4];
    const float* Wl2 = (const float*)d_in[5];
    const float* bl2 = (const float*)d_in[6];
    const float* Wr2 = (const float*)d_in[7];
    float*       out = (float*)d_out;

    float *xw, *xr, *aggr1, *h, *hw, *hr, *aggr2, *cnt;
    cudaGetSymbolAddress((void**)&xw,    g_xw);
    cudaGetSymbolAddress((void**)&xr,    g_xr);
    cudaGetSymbolAddress((void**)&aggr1, g_aggr1);
    cudaGetSymbolAddress((void**)&h,     g_h);
    cudaGetSymbolAddress((void**)&hw,    g_hw);
    cudaGetSymbolAddress((void**)&hr,    g_hr);
    cudaGetSymbolAddress((void**)&aggr2, g_aggr2);
    cudaGetSymbolAddress((void**)&cnt,   g_cnt);

    cudaMemsetAsync(aggr1, 0, sizeof(float) * N_NODES * 64, 0);
    cudaMemsetAsync(aggr2, 0, sizeof(float) * N_NODES * 32, 0);
    cudaMemsetAsync(cnt,   0, sizeof(float) * N_NODES,      0);

    const int eb64 = (N_EDGES * 16 + 255) / 256;
    const int eb32 = (N_EDGES * 8  + 255) / 256;
    const int g64  = (N_NODES + 31) / 32;    // gemv_dual<64>: NPB=32
    const int g32  = (N_NODES + 63) / 64;    // gemv_dual<32>: NPB=64
    const int c64  = (N_NODES * 16 + 255) / 256;
    const int c32  = (N_NODES * 8  + 255) / 256;

    // Layer 1
    gemv_dual_kernel<64><<<g64, 256>>>(x, Wl1, Wr1, xw, xr);
    edge_aggregate_kernel<64><<<eb64, 256>>>(xw, ei, aggr1, cnt, 1);
    combine_kernel<64, true><<<c64, 256>>>(aggr1, xr, cnt, bl1, h);

    // Layer 2
    gemv_dual_kernel<32><<<g32, 256>>>(h, Wl2, Wr2, hw, hr);
    edge_aggregate_kernel<32><<<eb32, 256>>>(hw, ei, aggr2, cnt, 0);
    combine_kernel<32, false><<<c32, 256>>>(aggr2, hr, cnt, bl2, out);
}

// round 16
// speedup vs baseline: 1.3495x; 1.3495x over previous
#include <cuda_runtime.h>
#include <cstdint>

#define N_NODES 50000
#define N_EDGES 800000

// Scratch: __device__ globals (allocation is forbidden)
__device__ __align__(16) float g_xw[N_NODES * 64];     // x @ Wl1^T
__device__ __align__(16) float g_xr[N_NODES * 64];     // x @ Wr1^T
__device__ __align__(16) float g_aggr1[N_NODES * 64];  // segsum(xw)
__device__ __align__(16) float g_h[N_NODES * 64];      // layer-1 output
__device__ __align__(16) float g_hw[N_NODES * 32];     // h @ Wl2^T
__device__ __align__(16) float g_hr[N_NODES * 32];     // h @ Wr2^T
__device__ __align__(16) float g_aggr2[N_NODES * 32];  // segsum(hw)
__device__ __align__(16) float g_cnt[N_NODES];
// Pre-transposed weights: Wt[k*OUT + t] = W[t*IN + k]
__device__ __align__(16) float g_Wl1t[64 * 64];
__device__ __align__(16) float g_Wr1t[64 * 64];
__device__ __align__(16) float g_Wl2t[64 * 32];
__device__ __align__(16) float g_Wr2t[64 * 32];

// ---------------------------------------------------------------------------
// One-shot weight transpose: Wt[k*OUT + t] = W[t*IN + k].
// 48KB total data, single small launch; removes the per-block scattered
// transpose that dominated R14's gemv profile (L1=71% from 32-sector LDGs).
// ---------------------------------------------------------------------------
template <int OUT>
__global__ void transpose_w_kernel(const float* __restrict__ Wa,
                                   const float* __restrict__ Wb,
                                   float* __restrict__ Wat,
                                   float* __restrict__ Wbt)
{
    constexpr int IN = 64;
    int i = blockIdx.x * blockDim.x + threadIdx.x;
    if (i >= IN * OUT) return;
    int t = i % OUT;
    int k = i / OUT;
    Wat[i] = Wa[t * IN + k];
    Wbt[i] = Wb[t * IN + k];
}

// ---------------------------------------------------------------------------
// Edge aggregation, F-dim rows: thread = (edge, float4 chunk).
// red.global.add.v4.f32 no-return reductions.
// ---------------------------------------------------------------------------
template <int F>
__global__ void edge_aggregate_kernel(const float* __restrict__ feat,
                                      const int* __restrict__ ei,
                                      float* __restrict__ aggr,
                                      float* __restrict__ cnt,
                                      int do_count)
{
    constexpr int C   = F / 4;
    constexpr int LOG = (F == 64) ? 4 : 3;
    int idx = blockIdx.x * blockDim.x + threadIdx.x;
    const int total = N_EDGES * C;
    if (idx >= total) return;
    int e = idx >> LOG;
    int c = idx & (C - 1);

    int src = ei[e];
    int dst = ei[N_EDGES + e];

    float4 v = __ldg((const float4*)(feat + (size_t)src * F) + c);

    float* p = aggr + (size_t)dst * F + c * 4;
    asm volatile("red.global.add.v4.f32 [%0], {%1, %2, %3, %4};"
                 :: "l"(p), "f"(v.x), "f"(v.y), "f"(v.z), "f"(v.w)
                 : "memory");

    if (do_count && c == 0) {
        atomicAdd(cnt + dst, 1.0f);
    }
}

// Component permute: out[i] = in[i ^ p], p in {0,1,2,3}
__device__ __forceinline__ float4 perm4(float4 v, int p)
{
    if (p & 1) { float t = v.x; v.x = v.y; v.y = t; t = v.z; v.z = v.w; v.w = t; }
    if (p & 2) { float t = v.x; v.x = v.z; v.z = t; t = v.y; v.y = v.w; v.w = t; }
    return v;
}

// ---------------------------------------------------------------------------
// Dual GEMV: ya = x@Wa^T, yb = x@Wb^T in ONE pass over x.
// Weights arrive PRE-TRANSPOSED -> staging is a coalesced float4 copy
// (R14's per-block scattered transpose was the actual L1 bottleneck).
// Inner loop unchanged from R14 (validated layout):
//  - warp = 32 nodes (lane = node) x one 8-output slice
//  - weight LDS.128s warp-uniform broadcasts
//  - feature scalar k of node nl at nl*64 + (k ^ (nl&31)) -> conflict-free
// ---------------------------------------------------------------------------
template <int OUT>
__global__ void __launch_bounds__(256)
gemv_dual_kernel(const float* __restrict__ x,
                 const float* __restrict__ Wat,   // [k*OUT + t]
                 const float* __restrict__ Wbt,
                 float* __restrict__ ya,
                 float* __restrict__ yb)
{
    constexpr int IN     = 64;
    constexpr int SLICES = OUT / 8;       // 8 (OUT=64) or 4 (OUT=32)
    constexpr int GROUPS = 8 / SLICES;    // 1 or 2
    constexpr int NPB    = 32 * GROUPS;   // 32 or 64 nodes per block

    __shared__ float sWa[IN * OUT];
    __shared__ float sWb[IN * OUT];
    __shared__ float sx[NPB * IN];        // swizzled feature rows
    // OUT=64: 16K+16K+8K = 40K;  OUT=32: 8K+8K+16K = 32K

    const int tid   = threadIdx.x;
    const int wid   = tid >> 5;
    const int lane  = tid & 31;
    const int slice = wid % SLICES;
    const int group = wid / SLICES;
    const int nloc  = group * 32 + lane;  // nloc & 31 == lane

    // Coalesced float4 weight staging (pre-transposed in gmem)
    for (int i = tid; i < (IN * OUT) / 4; i += 256) {
        ((float4*)sWa)[i] = __ldg((const float4*)Wat + i);
        ((float4*)sWb)[i] = __ldg((const float4*)Wbt + i);
    }

    // Stage feature rows, scalar-XOR swizzled
    const int base = blockIdx.x * NPB;
    for (int i = tid; i < NPB * (IN / 4); i += 256) {
        int nl = i / (IN / 4);
        int kq = i % (IN / 4);
        int n  = base + nl;
        if (n < N_NODES) {
            float4 xv = __ldg((const float4*)(x + (size_t)n * IN + kq * 4));
            int m    = nl & 31;
            int slot = kq ^ (m >> 2);
            ((float4*)(sx + nl * IN))[slot] = perm4(xv, m & 3);
        }
    }
    __syncthreads();

    int n = base + nloc;
    if (n >= N_NODES) return;

    float4 a0 = {0,0,0,0}, a1 = {0,0,0,0};   // Wa accumulators (8 outputs)
    float4 c0 = {0,0,0,0}, c1 = {0,0,0,0};   // Wb accumulators
    const float* px = sx + nloc * IN;
#pragma unroll 8
    for (int k = 0; k < IN; k++) {
        float xv = px[k ^ lane];
        const float4* wa = (const float4*)(sWa + k * OUT + slice * 8);
        const float4* wb = (const float4*)(sWb + k * OUT + slice * 8);
        float4 wa0 = wa[0], wa1 = wa[1];
        float4 wb0 = wb[0], wb1 = wb[1];
        a0.x += xv * wa0.x; a0.y += xv * wa0.y;
        a0.z += xv * wa0.z; a0.w += xv * wa0.w;
        a1.x += xv * wa1.x; a1.y += xv * wa1.y;
        a1.z += xv * wa1.z; a1.w += xv * wa1.w;
        c0.x += xv * wb0.x; c0.y += xv * wb0.y;
        c0.z += xv * wb0.z; c0.w += xv * wb0.w;
        c1.x += xv * wb1.x; c1.y += xv * wb1.y;
        c1.z += xv * wb1.z; c1.w += xv * wb1.w;
    }
    float4* pa = (float4*)(ya + (size_t)n * OUT + slice * 8);
    float4* pb = (float4*)(yb + (size_t)n * OUT + slice * 8);
    pa[0] = a0; pa[1] = a1;
    pb[0] = c0; pb[1] = c1;
}

// ---------------------------------------------------------------------------
// Elementwise combine: y = act( aggr/max(cnt,1) + bias + xr )
// ---------------------------------------------------------------------------
template <int F, bool RELU>
__global__ void combine_kernel(const float* __restrict__ aggr,
                               const float* __restrict__ xr,
                               const float* __restrict__ cnt,
                               const float* __restrict__ bias,
                               float* __restrict__ y)
{
    constexpr int C = F / 4;
    int idx = blockIdx.x * blockDim.x + threadIdx.x;
    const int total = N_NODES * C;
    if (idx >= total) return;
    int n = idx / C;
    int q = idx % C;

    float inv = 1.0f / fmaxf(__ldg(&cnt[n]), 1.0f);
    float4 a = __ldg((const float4*)aggr + idx);
    float4 r = __ldg((const float4*)xr + idx);
    float4 b = __ldg((const float4*)bias + q);

    float4 o;
    o.x = a.x * inv + b.x + r.x;
    o.y = a.y * inv + b.y + r.y;
    o.z = a.z * inv + b.z + r.z;
    o.w = a.w * inv + b.w + r.w;
    if (RELU) {
        o.x = fmaxf(o.x, 0.f); o.y = fmaxf(o.y, 0.f);
        o.z = fmaxf(o.z, 0.f); o.w = fmaxf(o.w, 0.f);
    }
    ((float4*)y)[idx] = o;
}

// ---------------------------------------------------------------------------
// Launch. Transform-then-aggregate (segment_sum is linear):
//  L1: {xw,xr} = x@{Wl1,Wr1}^T; aggr1 = segsum(xw); h = relu(aggr1/cnt+bl1+xr)
//  L2: {hw,hr} = h@{Wl2,Wr2}^T; aggr2 = segsum(hw); out = aggr2/cnt+bl2+hr
// ---------------------------------------------------------------------------
extern "C" void kernel_launch(void* const* d_in, const int* in_sizes, int n_in,
                              void* d_out, int out_size)
{
    const float* x   = (const float*)d_in[0];
    const int*   ei  = (const int*)d_in[1];
    const float* Wl1 = (const float*)d_in[2];
    const float* bl1 = (const float*)d_in[3];
    const float* Wr1 = (const float*)d_in[4];
    const float* Wl2 = (const float*)d_in[5];
    const float* bl2 = (const float*)d_in[6];
    const float* Wr2 = (const float*)d_in[7];
    float*       out = (float*)d_out;

    float *xw, *xr, *aggr1, *h, *hw, *hr, *aggr2, *cnt;
    float *Wl1t, *Wr1t, *Wl2t, *Wr2t;
    cudaGetSymbolAddress((void**)&xw,    g_xw);
    cudaGetSymbolAddress((void**)&xr,    g_xr);
    cudaGetSymbolAddress((void**)&aggr1, g_aggr1);
    cudaGetSymbolAddress((void**)&h,     g_h);
    cudaGetSymbolAddress((void**)&hw,    g_hw);
    cudaGetSymbolAddress((void**)&hr,    g_hr);
    cudaGetSymbolAddress((void**)&aggr2, g_aggr2);
    cudaGetSymbolAddress((void**)&cnt,   g_cnt);
    cudaGetSymbolAddress((void**)&Wl1t,  g_Wl1t);
    cudaGetSymbolAddress((void**)&Wr1t,  g_Wr1t);
    cudaGetSymbolAddress((void**)&Wl2t,  g_Wl2t);
    cudaGetSymbolAddress((void**)&Wr2t,  g_Wr2t);

    cudaMemsetAsync(aggr1, 0, sizeof(float) * N_NODES * 64, 0);
    cudaMemsetAsync(aggr2, 0, sizeof(float) * N_NODES * 32, 0);
    cudaMemsetAsync(cnt,   0, sizeof(float) * N_NODES,      0);

    // One-shot weight transposes (tiny)
    transpose_w_kernel<64><<<16, 256>>>(Wl1, Wr1, Wl1t, Wr1t);
    transpose_w_kernel<32><<<8,  256>>>(Wl2, Wr2, Wl2t, Wr2t);

    const int eb64 = (N_EDGES * 16 + 255) / 256;
    const int eb32 = (N_EDGES * 8  + 255) / 256;
    const int g64  = (N_NODES + 31) / 32;    // gemv_dual<64>: NPB=32
    const int g32  = (N_NODES + 63) / 64;    // gemv_dual<32>: NPB=64
    const int c64  = (N_NODES * 16 + 255) / 256;
    const int c32  = (N_NODES * 8  + 255) / 256;

    // Layer 1
    gemv_dual_kernel<64><<<g64, 256>>>(x, Wl1t, Wr1t, xw, xr);
    edge_aggregate_kernel<64><<<eb64, 256>>>(xw, ei, aggr1, cnt, 1);
    combine_kernel<64, true><<<c64, 256>>>(aggr1, xr, cnt, bl1, h);

    // Layer 2
    gemv_dual_kernel<32><<<g32, 256>>>(h, Wl2t, Wr2t, hw, hr);
    edge_aggregate_kernel<32><<<eb32, 256>>>(hw, ei, aggr2, cnt, 0);
    combine_kernel<32, false><<<c32, 256>>>(aggr2, hr, cnt, bl2, out);
}